// round 9
// baseline (speedup 1.0000x reference)
#include <cuda_runtime.h>

// PLIF spiking neuron forward — round 9: 8-deep v8 bursts at forced 3 blocks/SM.
// x: [B=16, T=32, C=128, H=32, W=32] fp32; a scalar; out spikes fp32 {0,1}.
//
// Established: burst depth 8 is optimal; at fixed depth, DRAM efficiency
// tracks occupancy (16.4% occ -> 75.6%, 21.7% -> 76.4%). This round keeps
// the round-6 structure but caps registers via __launch_bounds__(256, 3)
// (<=85 regs) to fit 3 blocks/SM (~37.5% theoretical occ). Spikes overwrite
// the load payload registers in place; addressing relies on base+immediate
// (t-stride*4B <= 3.7MB fits LDG's 24-bit immediate).

constexpr int B = 16;
constexpr int T = 32;
constexpr int C = 128;
constexpr int H = 32;
constexpr int W = 32;
constexpr int CHW      = C * H * W;          // 131072 floats per (b,t) slice
constexpr int CHW_V8   = CHW / 8;            // 16384 v8 chunks per slice
constexpr int TOTAL_V8 = B * CHW_V8;         // 262144 v8 sites
constexpr int DEPTH    = 8;

__device__ __forceinline__ void ldg256_cs(const float* p, float* v)
{
    asm volatile(
        "ld.global.cs.v8.f32 {%0,%1,%2,%3,%4,%5,%6,%7}, [%8];"
        : "=f"(v[0]), "=f"(v[1]), "=f"(v[2]), "=f"(v[3]),
          "=f"(v[4]), "=f"(v[5]), "=f"(v[6]), "=f"(v[7])
        : "l"(p));
}

__device__ __forceinline__ void stg256_cs(float* p, const float* v)
{
    asm volatile(
        "st.global.cs.v8.f32 [%0], {%1,%2,%3,%4,%5,%6,%7,%8};"
        :: "l"(p),
           "f"(v[0]), "f"(v[1]), "f"(v[2]), "f"(v[3]),
           "f"(v[4]), "f"(v[5]), "f"(v[6]), "f"(v[7])
        : "memory");
}

__global__ __launch_bounds__(256, 3)
void plif_fwd_kernel(const float* __restrict__ x,
                     const float* __restrict__ a,
                     float*       __restrict__ out)
{
    int i = blockIdx.x * blockDim.x + threadIdx.x;
    if (i >= TOTAL_V8) return;

    int b    = i >> 14;                // i / CHW_V8
    int chw8 = i & (CHW_V8 - 1);
    long long base = (long long)b * (T * CHW) + (long long)chw8 * 8;

    const float* xp = x + base;
    float*       op = out + base;

    float av = __ldg(a);
    float decay = 1.0f / (1.0f + expf(-av));

    float mem[8];
    #pragma unroll
    for (int e = 0; e < 8; e++) mem[e] = 0.0f;

    #pragma unroll
    for (int tb = 0; tb < T; tb += DEPTH) {
        float xi[DEPTH][8];

        // 8-deep read burst: 8 independent LDG.E.256 (8KB/warp) in flight.
        #pragma unroll
        for (int u = 0; u < DEPTH; u++)
            ldg256_cs(xp + (long long)(tb + u) * CHW, xi[u]);

        // Recurrence + spike + hard reset; spikes overwrite xi in place.
        #pragma unroll
        for (int u = 0; u < DEPTH; u++) {
            #pragma unroll
            for (int e = 0; e < 8; e++) {
                mem[e] = fmaf(decay, mem[e], xi[u][e]);
                bool fire = (mem[e] >= 1.0f);
                xi[u][e] = fire ? 1.0f : 0.0f;
                mem[e]   = fire ? 0.0f : mem[e];
            }
        }

        // 8-deep write burst.
        #pragma unroll
        for (int u = 0; u < DEPTH; u++)
            stg256_cs(op + (long long)(tb + u) * CHW, xi[u]);
    }
}

extern "C" void kernel_launch(void* const* d_in, const int* in_sizes, int n_in,
                              void* d_out, int out_size)
{
    const float* x   = (const float*)d_in[0];
    const float* a   = (const float*)d_in[1];
    float*       out = (float*)d_out;

    constexpr int THREADS = 256;
    constexpr int BLOCKS  = (TOTAL_V8 + THREADS - 1) / THREADS;  // 1024

    plif_fwd_kernel<<<BLOCKS, THREADS>>>(x, a, out);
}

// round 10
// speedup vs baseline: 1.0277x; 1.0277x over previous
#include <cuda_runtime.h>

// PLIF spiking neuron forward — round 10: exact round-6 structure (best
// measured: 77.6us kernel / 76.4% DRAM), single change: 128-thread blocks
// -> 5 resident blocks/SM (20 warps, ~31% occ) with UNCONSTRAINED registers
// so ptxas keeps the contiguous 8x LDG.E.256 burst intact (round 9 showed
// reg-capping breaks the burst scheduling and costs ~2pt of DRAM eff).
// x: [B=16, T=32, C=128, H=32, W=32] fp32; a scalar; out spikes fp32 {0,1}.

constexpr int B = 16;
constexpr int T = 32;
constexpr int C = 128;
constexpr int H = 32;
constexpr int W = 32;
constexpr int CHW      = C * H * W;          // 131072 floats per (b,t) slice
constexpr int CHW_V8   = CHW / 8;            // 16384 v8 chunks per slice
constexpr int TOTAL_V8 = B * CHW_V8;         // 262144 v8 sites
constexpr int UNROLL   = 8;

__device__ __forceinline__ void ldg256_cs(const float* p, float* v)
{
    asm volatile(
        "ld.global.cs.v8.f32 {%0,%1,%2,%3,%4,%5,%6,%7}, [%8];"
        : "=f"(v[0]), "=f"(v[1]), "=f"(v[2]), "=f"(v[3]),
          "=f"(v[4]), "=f"(v[5]), "=f"(v[6]), "=f"(v[7])
        : "l"(p));
}

__device__ __forceinline__ void stg256_cs(float* p, const float* v)
{
    asm volatile(
        "st.global.cs.v8.f32 [%0], {%1,%2,%3,%4,%5,%6,%7,%8};"
        :: "l"(p),
           "f"(v[0]), "f"(v[1]), "f"(v[2]), "f"(v[3]),
           "f"(v[4]), "f"(v[5]), "f"(v[6]), "f"(v[7])
        : "memory");
}

__global__ __launch_bounds__(128)
void plif_fwd_kernel(const float* __restrict__ x,
                     const float* __restrict__ a,
                     float*       __restrict__ out)
{
    int i = blockIdx.x * blockDim.x + threadIdx.x;
    if (i >= TOTAL_V8) return;

    int b    = i >> 14;                // i / CHW_V8
    int chw8 = i & (CHW_V8 - 1);
    long long base = (long long)b * (T * CHW) + (long long)chw8 * 8;

    float av = __ldg(a);
    float decay = 1.0f / (1.0f + expf(-av));

    float mem[8];
    #pragma unroll
    for (int e = 0; e < 8; e++) mem[e] = 0.0f;

    #pragma unroll
    for (int tb = 0; tb < T; tb += UNROLL) {
        float xi[UNROLL][8];

        // 8-deep read burst: 8 independent LDG.E.256 (8KB/warp) in flight.
        #pragma unroll
        for (int u = 0; u < UNROLL; u++)
            ldg256_cs(x + base + (long long)(tb + u) * CHW, xi[u]);

        // Recurrence + spike + hard reset, then per-step v8 store
        // (identical compute/store shape to round 6 — separate s temp).
        #pragma unroll
        for (int u = 0; u < UNROLL; u++) {
            float s[8];
            #pragma unroll
            for (int e = 0; e < 8; e++) {
                mem[e] = fmaf(decay, mem[e], xi[u][e]);
                bool fire = (mem[e] >= 1.0f);
                s[e]   = fire ? 1.0f : 0.0f;
                mem[e] = fire ? 0.0f : mem[e];
            }
            stg256_cs(out + base + (long long)(tb + u) * CHW, s);
        }
    }
}

extern "C" void kernel_launch(void* const* d_in, const int* in_sizes, int n_in,
                              void* d_out, int out_size)
{
    const float* x   = (const float*)d_in[0];
    const float* a   = (const float*)d_in[1];
    float*       out = (float*)d_out;

    constexpr int THREADS = 128;
    constexpr int BLOCKS  = (TOTAL_V8 + THREADS - 1) / THREADS;  // 2048

    plif_fwd_kernel<<<BLOCKS, THREADS>>>(x, a, out);
}

// round 11
// speedup vs baseline: 1.0307x; 1.0029x over previous
#include <cuda_runtime.h>

// PLIF spiking neuron forward — FINAL (round-6 configuration, reverted).
// x: [B=16, T=32, C=128, H=32, W=32] fp32; a scalar (decay = sigmoid(a));
// out: spikes fp32 {0,1}, same shape.
//
// Measured optimum across 10 configurations on sm_100a:
//   77.6us kernel / 76.4% DRAM / 6251 GB/s (bench ~86.4us).
// Winning ingredients:
//   - 256-bit (v8.f32) global loads/stores with .cs streaming hint
//   - 8-deep front-batched read burst (8x LDG.E.256 = 8KB/warp) — the MC
//     burst-depth dose-response peaks here (73.0% @2KB -> 76.4% @8KB,
//     regresses at 16KB)
//   - per-step v8 store with separate spike temp; 256-thread blocks;
//     NO launch-bounds reg cap (capping reschedules/breaks the burst)
// Falsified levers: MLP/occupancy (43-84% occ identical), per-warp R/W
// phasing, persistent single-wave grid (regressed), software pipelining,
// forced higher occupancy (both reg-capped and 128-thr variants regressed).

constexpr int B = 16;
constexpr int T = 32;
constexpr int C = 128;
constexpr int H = 32;
constexpr int W = 32;
constexpr int CHW      = C * H * W;          // 131072 floats per (b,t) slice
constexpr int CHW_V8   = CHW / 8;            // 16384 v8 chunks per slice
constexpr int TOTAL_V8 = B * CHW_V8;         // 262144 v8 sites
constexpr int UNROLL   = 8;

__device__ __forceinline__ void ldg256_cs(const float* p, float* v)
{
    asm volatile(
        "ld.global.cs.v8.f32 {%0,%1,%2,%3,%4,%5,%6,%7}, [%8];"
        : "=f"(v[0]), "=f"(v[1]), "=f"(v[2]), "=f"(v[3]),
          "=f"(v[4]), "=f"(v[5]), "=f"(v[6]), "=f"(v[7])
        : "l"(p));
}

__device__ __forceinline__ void stg256_cs(float* p, const float* v)
{
    asm volatile(
        "st.global.cs.v8.f32 [%0], {%1,%2,%3,%4,%5,%6,%7,%8};"
        :: "l"(p),
           "f"(v[0]), "f"(v[1]), "f"(v[2]), "f"(v[3]),
           "f"(v[4]), "f"(v[5]), "f"(v[6]), "f"(v[7])
        : "memory");
}

__global__ __launch_bounds__(256)
void plif_fwd_kernel(const float* __restrict__ x,
                     const float* __restrict__ a,
                     float*       __restrict__ out)
{
    int i = blockIdx.x * blockDim.x + threadIdx.x;
    if (i >= TOTAL_V8) return;

    int b    = i >> 14;                // i / CHW_V8
    int chw8 = i & (CHW_V8 - 1);
    long long base = (long long)b * (T * CHW) + (long long)chw8 * 8;

    float av = __ldg(a);
    float decay = 1.0f / (1.0f + expf(-av));

    float mem[8];
    #pragma unroll
    for (int e = 0; e < 8; e++) mem[e] = 0.0f;

    #pragma unroll
    for (int tb = 0; tb < T; tb += UNROLL) {
        float xi[UNROLL][8];

        // 8-deep read burst: 8 independent LDG.E.256 (8KB/warp) in flight.
        #pragma unroll
        for (int u = 0; u < UNROLL; u++)
            ldg256_cs(x + base + (long long)(tb + u) * CHW, xi[u]);

        // Recurrence + spike + hard reset, then 256-bit store per step.
        #pragma unroll
        for (int u = 0; u < UNROLL; u++) {
            float s[8];
            #pragma unroll
            for (int e = 0; e < 8; e++) {
                mem[e] = fmaf(decay, mem[e], xi[u][e]);
                bool fire = (mem[e] >= 1.0f);
                s[e]   = fire ? 1.0f : 0.0f;
                mem[e] = fire ? 0.0f : mem[e];
            }
            stg256_cs(out + base + (long long)(tb + u) * CHW, s);
        }
    }
}

extern "C" void kernel_launch(void* const* d_in, const int* in_sizes, int n_in,
                              void* d_out, int out_size)
{
    const float* x   = (const float*)d_in[0];
    const float* a   = (const float*)d_in[1];
    float*       out = (float*)d_out;

    constexpr int THREADS = 256;
    constexpr int BLOCKS  = (TOTAL_V8 + THREADS - 1) / THREADS;  // 1024

    plif_fwd_kernel<<<BLOCKS, THREADS>>>(x, a, out);
}

// round 12
// speedup vs baseline: 1.0480x; 1.0167x over previous
#include <cuda_runtime.h>

// PLIF spiking neuron forward — round 12: champion (depth-8 v8, 256 thr,
// uncapped regs) with the ONE untested variation: phase-batched write burst
// (8 back-to-back STG.E.256 after the compute phase) + in-place spikes.
// Mechanism under test: MC write-burst run-length, mirroring the read-burst
// dose-response that produced every win so far (73.0% @2KB -> 76.4% @8KB).
// x: [B=16, T=32, C=128, H=32, W=32] fp32; a scalar; out spikes fp32 {0,1}.

constexpr int B = 16;
constexpr int T = 32;
constexpr int C = 128;
constexpr int H = 32;
constexpr int W = 32;
constexpr int CHW      = C * H * W;          // 131072 floats per (b,t) slice
constexpr int CHW_V8   = CHW / 8;            // 16384 v8 chunks per slice
constexpr int TOTAL_V8 = B * CHW_V8;         // 262144 v8 sites
constexpr int UNROLL   = 8;

__device__ __forceinline__ void ldg256_cs(const float* p, float* v)
{
    asm volatile(
        "ld.global.cs.v8.f32 {%0,%1,%2,%3,%4,%5,%6,%7}, [%8];"
        : "=f"(v[0]), "=f"(v[1]), "=f"(v[2]), "=f"(v[3]),
          "=f"(v[4]), "=f"(v[5]), "=f"(v[6]), "=f"(v[7])
        : "l"(p));
}

__device__ __forceinline__ void stg256_cs(float* p, const float* v)
{
    asm volatile(
        "st.global.cs.v8.f32 [%0], {%1,%2,%3,%4,%5,%6,%7,%8};"
        :: "l"(p),
           "f"(v[0]), "f"(v[1]), "f"(v[2]), "f"(v[3]),
           "f"(v[4]), "f"(v[5]), "f"(v[6]), "f"(v[7])
        : "memory");
}

__global__ __launch_bounds__(256)
void plif_fwd_kernel(const float* __restrict__ x,
                     const float* __restrict__ a,
                     float*       __restrict__ out)
{
    int i = blockIdx.x * blockDim.x + threadIdx.x;
    if (i >= TOTAL_V8) return;

    int b    = i >> 14;                // i / CHW_V8
    int chw8 = i & (CHW_V8 - 1);
    long long base = (long long)b * (T * CHW) + (long long)chw8 * 8;

    float av = __ldg(a);
    float decay = 1.0f / (1.0f + expf(-av));

    float mem[8];
    #pragma unroll
    for (int e = 0; e < 8; e++) mem[e] = 0.0f;

    #pragma unroll
    for (int tb = 0; tb < T; tb += UNROLL) {
        float xi[UNROLL][8];

        // Phase 1 — read burst: 8 independent LDG.E.256 (8KB/warp).
        #pragma unroll
        for (int u = 0; u < UNROLL; u++)
            ldg256_cs(x + base + (long long)(tb + u) * CHW, xi[u]);

        // Phase 2 — recurrence + spike + hard reset, spikes in place.
        #pragma unroll
        for (int u = 0; u < UNROLL; u++) {
            #pragma unroll
            for (int e = 0; e < 8; e++) {
                mem[e] = fmaf(decay, mem[e], xi[u][e]);
                bool fire = (mem[e] >= 1.0f);
                xi[u][e] = fire ? 1.0f : 0.0f;
                mem[e]   = fire ? 0.0f : mem[e];
            }
        }

        // Phase 3 — write burst: 8 back-to-back STG.E.256 (8KB/warp).
        #pragma unroll
        for (int u = 0; u < UNROLL; u++)
            stg256_cs(out + base + (long long)(tb + u) * CHW, xi[u]);
    }
}

extern "C" void kernel_launch(void* const* d_in, const int* in_sizes, int n_in,
                              void* d_out, int out_size)
{
    const float* x   = (const float*)d_in[0];
    const float* a   = (const float*)d_in[1];
    float*       out = (float*)d_out;

    constexpr int THREADS = 256;
    constexpr int BLOCKS  = (TOTAL_V8 + THREADS - 1) / THREADS;  // 1024

    plif_fwd_kernel<<<BLOCKS, THREADS>>>(x, a, out);
}